// round 8
// baseline (speedup 1.0000x reference)
#include <cuda_runtime.h>
#include <math.h>
#include <cstdint>

#define BSZ   4096
#define DIM   768
#define COMPS 16384
#define GRD   128

// column split: tensor tiles are 128 wide, fma tiles 128 wide
#define TEN_TILES 88
#define FMA_TILES 40
#define TEN_CTAS  (TEN_TILES * 32)   // 2816
#define TOT_CTAS  4096
#define FMA_COL0  (TEN_TILES * 128)  // 11264

// ---------------- device scratch ----------------
__device__ float g_T[COMPS * DIM];
__device__ float g_wn[COMPS];
__device__ float g_cnt[COMPS];
__device__ float g_s1[COMPS];
__device__ float g_s[COMPS];
__device__ float g_G[GRD * GRD];
__device__ int   g_bmu[BSZ];
__device__ unsigned g_maxX, g_maxW;
__device__ __align__(16) signed char g_Xq[BSZ * DIM];
__device__ __align__(16) signed char g_Wq[COMPS * DIM];
__device__ __align__(16) short g_d2q[(size_t)BSZ * COMPS];   // approx d2 * 4

// ---------------- helpers ----------------
__device__ __forceinline__ uint32_t smem_to_u32(const void* p) {
    uint32_t a;
    asm("{ .reg .u64 t; cvta.to.shared.u64 t, %1; cvt.u32.u64 %0, t; }" : "=r"(a) : "l"(p));
    return a;
}
__device__ __forceinline__ void cp_async16(uint32_t dst, const void* src) {
    asm volatile("cp.async.cg.shared.global [%0], [%1], 16;" :: "r"(dst), "l"(src));
}
__device__ __forceinline__ uint32_t lds32(uint32_t a) {
    uint32_t v;
    asm volatile("ld.shared.b32 %0, [%1];" : "=r"(v) : "r"(a));
    return v;
}
__device__ __forceinline__ void mma_s8(int* d, const uint32_t* a, const uint32_t* b) {
    asm volatile(
        "mma.sync.aligned.m16n8k32.row.col.s32.s8.s8.s32 "
        "{%0,%1,%2,%3}, {%4,%5,%6,%7}, {%8,%9}, {%0,%1,%2,%3};"
        : "+r"(d[0]), "+r"(d[1]), "+r"(d[2]), "+r"(d[3])
        : "r"(a[0]), "r"(a[1]), "r"(a[2]), "r"(a[3]), "r"(b[0]), "r"(b[1]));
}
__device__ __forceinline__ unsigned long long pack2(float lo, float hi) {
    unsigned long long r;
    asm("mov.b64 %0, {%1, %2};" : "=l"(r) : "r"(__float_as_uint(lo)), "r"(__float_as_uint(hi)));
    return r;
}
__device__ __forceinline__ void ffma2(unsigned long long& d, unsigned long long a,
                                      unsigned long long b) {
    asm("fma.rn.f32x2 %0, %1, %2, %0;" : "+l"(d) : "l"(a), "l"(b));
}

// ---------------- pre kernels ----------------
#define XN4 (BSZ * DIM / 4)
#define WN4 (COMPS * DIM / 4)
__global__ void absmax2_kernel(const float* __restrict__ X, const float* __restrict__ W) {
    __shared__ float rx[256], rw[256];
    float mx = 0.f, mw = 0.f;
    int stride = gridDim.x * blockDim.x;
    for (int i = blockIdx.x * blockDim.x + threadIdx.x; i < XN4 + WN4; i += stride) {
        float4 v = (i < XN4) ? *(const float4*)(X + (size_t)i * 4)
                             : *(const float4*)(W + (size_t)(i - XN4) * 4);
        float m = fmaxf(fmaxf(fabsf(v.x), fabsf(v.y)), fmaxf(fabsf(v.z), fabsf(v.w)));
        if (i < XN4) mx = fmaxf(mx, m); else mw = fmaxf(mw, m);
    }
    rx[threadIdx.x] = mx; rw[threadIdx.x] = mw;
    __syncthreads();
    for (int s = 128; s; s >>= 1) {
        if (threadIdx.x < s) {
            rx[threadIdx.x] = fmaxf(rx[threadIdx.x], rx[threadIdx.x + s]);
            rw[threadIdx.x] = fmaxf(rw[threadIdx.x], rw[threadIdx.x + s]);
        }
        __syncthreads();
    }
    if (threadIdx.x == 0) {
        atomicMax(&g_maxX, __float_as_uint(rx[0]));
        atomicMax(&g_maxW, __float_as_uint(rw[0]));
    }
}

__global__ void quantX_kernel(const float* __restrict__ src) {
    int i = blockIdx.x * blockDim.x + threadIdx.x;
    if (i >= XN4) return;
    float inv = 127.f / __uint_as_float(g_maxX);
    float4 v = *(const float4*)(src + (size_t)i * 4);
    float x[4] = {v.x, v.y, v.z, v.w};
    unsigned pk = 0;
    #pragma unroll
    for (int k = 0; k < 4; k++) {
        int q = __float2int_rn(x[k] * inv);
        q = max(-127, min(127, q));
        pk |= ((unsigned)(q & 0xFF)) << (k * 8);
    }
    *(unsigned*)(g_Xq + (size_t)i * 4) = pk;
}

__global__ void quantW_wnorm_kernel(const float* __restrict__ W) {
    int row = blockIdx.x * 8 + (threadIdx.x >> 5);
    int lane = threadIdx.x & 31;
    float inv = 127.f / __uint_as_float(g_maxW);
    const float* wr = W + (size_t)row * DIM;
    float s = 0.f;
    #pragma unroll
    for (int k = 0; k < 6; k++) {
        int e = lane * 4 + k * 128;
        float4 v = *(const float4*)(wr + e);
        float x[4] = {v.x, v.y, v.z, v.w};
        unsigned pk = 0;
        #pragma unroll
        for (int j = 0; j < 4; j++) {
            s = fmaf(x[j], x[j], s);
            int q = __float2int_rn(x[j] * inv);
            q = max(-127, min(127, q));
            pk |= ((unsigned)(q & 0xFF)) << (j * 8);
        }
        *(unsigned*)(g_Wq + (size_t)row * DIM + e) = pk;
    }
    #pragma unroll
    for (int o = 16; o; o >>= 1) s += __shfl_xor_sync(0xffffffffu, s, o);
    if (lane == 0) g_wn[row] = s;
}

__global__ void gmat_kernel(const int* __restrict__ itp) {
    float decay = 1.f - (float)(*itp) / 1000.f;
    float sig = 64.f * decay;
    int a = blockIdx.x, b = threadIdx.x;
    float d = (float)(a - b);
    g_G[a * GRD + b] = expf(-(d * d) / (sig * sig));
}

// ---------------- combined BMU GEMM: tensor CTAs + fma CTAs --------------
#define QPITCH  48
#define QT_TILE 6144
#define QSTAGE  12288            // A + B (128x128 tile)
#define QWNS    (4 * QSTAGE)     // 49152
#define QSMEM   (QWNS + 512)     // 49664

__global__ __launch_bounds__(256, 2) void bmu_combo_kernel(const float* __restrict__ X,
                                                           const float* __restrict__ W) {
    extern __shared__ char sm[];
    const uint32_t sb = smem_to_u32(sm);
    const int t = threadIdx.x;
    const int bid = blockIdx.x;
    // Bresenham interleave of 2816 tensor / 1280 fma blocks
    const int c0 = (int)(((long long)bid * TEN_CTAS) / TOT_CTAS);
    const int c1 = (int)(((long long)(bid + 1) * TEN_CTAS) / TOT_CTAS);

    if (c1 > c0) {
        // ---------------- tensor path: int8 mma, tile 128x128 ----------------
        const int bx = c0 % TEN_TILES, by = c0 / TEN_TILES;
        const int rowX = by * 128, rowW = bx * 128;
        const int lane = t & 31, w = t >> 5;
        const int wm = w >> 2, wn_ = w & 3;
        const int arow = lane >> 2, ac4 = (lane & 3) * 4;

        float* wns = (float*)(sm + QWNS);
        if (t < 128) wns[t] = g_wn[rowW + t];

        int acc[4][4][4];
        #pragma unroll
        for (int mi = 0; mi < 4; mi++)
            #pragma unroll
            for (int ni = 0; ni < 4; ni++)
                #pragma unroll
                for (int k = 0; k < 4; k++) acc[mi][ni][k] = 0;

        auto load_stage = [&](int s, int c) {
            uint32_t base = sb + s * QSTAGE;
            int r = t >> 1, g = t & 1;
            cp_async16(base + r * QPITCH + g * 16,
                       g_Xq + (size_t)(rowX + r) * DIM + c * 32 + g * 16);
            cp_async16(base + QT_TILE + r * QPITCH + g * 16,
                       g_Wq + (size_t)(rowW + r) * DIM + c * 32 + g * 16);
        };
        auto compute = [&](int s) {
            uint32_t Ah = sb + s * QSTAGE;
            uint32_t Bh = Ah + QT_TILE;
            uint32_t b[4][2];
            #pragma unroll
            for (int ni = 0; ni < 4; ni++) {
                uint32_t off = Bh + (uint32_t)((wn_ * 32 + ni * 8 + arow) * QPITCH + ac4);
                b[ni][0] = lds32(off); b[ni][1] = lds32(off + 16);
            }
            uint32_t a[4][4];
            #pragma unroll
            for (int mi = 0; mi < 4; mi++) {
                uint32_t off = Ah + (uint32_t)((wm * 64 + mi * 16 + arow) * QPITCH + ac4);
                a[mi][0] = lds32(off);      a[mi][1] = lds32(off + 8 * QPITCH);
                a[mi][2] = lds32(off + 16); a[mi][3] = lds32(off + 8 * QPITCH + 16);
            }
            #pragma unroll
            for (int mi = 0; mi < 4; mi++)
                #pragma unroll
                for (int ni = 0; ni < 4; ni++) mma_s8(acc[mi][ni], a[mi], b[ni]);
        };

        #pragma unroll
        for (int p = 0; p < 3; p++) { load_stage(p, p); asm volatile("cp.async.commit_group;"); }
        for (int c = 0; c < 24; c++) {
            asm volatile("cp.async.wait_group 2;");
            __syncthreads();
            if (c + 3 < 24) load_stage((c + 3) & 3, c + 3);
            asm volatile("cp.async.commit_group;");
            compute(c & 3);
        }

        float twoss = 2.f * (__uint_as_float(g_maxX) / 127.f) * (__uint_as_float(g_maxW) / 127.f);
        #pragma unroll
        for (int mi = 0; mi < 4; mi++) {
            int r0 = rowX + wm * 64 + mi * 16 + arow;
            #pragma unroll
            for (int ni = 0; ni < 4; ni++) {
                int col0 = wn_ * 32 + ni * 8 + (lane & 3) * 2;
                float w0 = wns[col0], w1 = wns[col0 + 1];
                #pragma unroll
                for (int h = 0; h < 2; h++) {
                    float d0 = (w0 - twoss * (float)acc[mi][ni][h * 2 + 0]) * 4.f;
                    float d1 = (w1 - twoss * (float)acc[mi][ni][h * 2 + 1]) * 4.f;
                    int q0 = __float2int_rn(fminf(fmaxf(d0, -32000.f), 32000.f));
                    int q1 = __float2int_rn(fminf(fmaxf(d1, -32000.f), 32000.f));
                    unsigned pk = (unsigned)(q0 & 0xFFFF) | ((unsigned)q1 << 16);
                    *(unsigned*)(g_d2q + (size_t)(r0 + h * 8) * COMPS + rowW + col0) = pk;
                }
            }
        }
    } else {
        // ---------------- fma path: fp32 f32x2, tile 128x128, exact d2 -------
        const int j = bid - c0;
        const int bx = j % FMA_TILES, by = j / FMA_TILES;
        const int rowX = by * 128;
        const int colW0 = FMA_COL0 + bx * 128;
        const int tx = t & 15, ty = t >> 4;

        float* Xs = (float*)sm;                    // [8][128]
        float* Ws = (float*)(sm + 4096);           // [8][128]
        float* wns = (float*)(sm + QWNS);
        if (t < 128) wns[t] = g_wn[colW0 + t];

        unsigned long long acc2[8][4];
        #pragma unroll
        for (int i = 0; i < 8; i++)
            #pragma unroll
            for (int g = 0; g < 4; g++) acc2[i][g] = 0ull;

        int lrow = t >> 1, lk4 = (t & 1) * 4;
        const float* Xp = X + (size_t)(rowX + lrow) * DIM + lk4;
        const float* Wp = W + (size_t)(colW0 + lrow) * DIM + lk4;

        for (int k0 = 0; k0 < DIM; k0 += 8) {
            float4 xv = *(const float4*)(Xp + k0);
            float4 wv = *(const float4*)(Wp + k0);
            if (k0) __syncthreads();
            Xs[(lk4 + 0) * 128 + lrow] = xv.x; Xs[(lk4 + 1) * 128 + lrow] = xv.y;
            Xs[(lk4 + 2) * 128 + lrow] = xv.z; Xs[(lk4 + 3) * 128 + lrow] = xv.w;
            Ws[(lk4 + 0) * 128 + lrow] = wv.x; Ws[(lk4 + 1) * 128 + lrow] = wv.y;
            Ws[(lk4 + 2) * 128 + lrow] = wv.z; Ws[(lk4 + 3) * 128 + lrow] = wv.w;
            __syncthreads();
            #pragma unroll
            for (int k = 0; k < 8; k++) {
                float4 b0 = *(const float4*)&Ws[k * 128 + tx * 4];
                float4 b1 = *(const float4*)&Ws[k * 128 + tx * 4 + 64];
                unsigned long long bp[4] = {pack2(b0.x, b0.y), pack2(b0.z, b0.w),
                                            pack2(b1.x, b1.y), pack2(b1.z, b1.w)};
                float4 a0 = *(const float4*)&Xs[k * 128 + ty * 4];
                float4 a1 = *(const float4*)&Xs[k * 128 + ty * 4 + 64];
                float av[8] = {a0.x, a0.y, a0.z, a0.w, a1.x, a1.y, a1.z, a1.w};
                #pragma unroll
                for (int i = 0; i < 8; i++) {
                    unsigned long long ap = pack2(av[i], av[i]);
                    #pragma unroll
                    for (int g = 0; g < 4; g++) ffma2(acc2[i][g], ap, bp[g]);
                }
            }
        }

        // exact d2 dump
        #pragma unroll
        for (int i = 0; i < 8; i++) {
            int row = rowX + ((i < 4) ? (ty * 4 + i) : (64 + ty * 4 + (i - 4)));
            #pragma unroll
            for (int gg = 0; gg < 2; gg++) {
                int cl = ((gg == 0) ? (tx * 4) : (64 + tx * 4));
                unsigned long long p0 = acc2[i][gg * 2], p1 = acc2[i][gg * 2 + 1];
                float d0 = (wns[cl + 0] - 2.f * __uint_as_float((unsigned)(p0 & 0xffffffffull))) * 4.f;
                float d1 = (wns[cl + 1] - 2.f * __uint_as_float((unsigned)(p0 >> 32))) * 4.f;
                float d2v = (wns[cl + 2] - 2.f * __uint_as_float((unsigned)(p1 & 0xffffffffull))) * 4.f;
                float d3 = (wns[cl + 3] - 2.f * __uint_as_float((unsigned)(p1 >> 32))) * 4.f;
                int q0 = __float2int_rn(fminf(fmaxf(d0, -32000.f), 32000.f));
                int q1 = __float2int_rn(fminf(fmaxf(d1, -32000.f), 32000.f));
                int q2 = __float2int_rn(fminf(fmaxf(d2v, -32000.f), 32000.f));
                int q3 = __float2int_rn(fminf(fmaxf(d3, -32000.f), 32000.f));
                uint2 pk;
                pk.x = (unsigned)(q0 & 0xFFFF) | ((unsigned)q1 << 16);
                pk.y = (unsigned)(q2 & 0xFFFF) | ((unsigned)q3 << 16);
                *(uint2*)(g_d2q + (size_t)row * COMPS + colW0 + cl) = pk;
            }
        }
    }
}

// ---------------- candidate rescue: min + margin scan + exact fp32 -------
#define MARGIN_Q 48
__global__ __launch_bounds__(256) void bmu_scan_kernel(const float* __restrict__ X,
                                                       const float* __restrict__ W) {
    __shared__ int red[256];
    __shared__ int cnt;
    __shared__ int cand[128];
    int row = blockIdx.x, t = threadIdx.x;
    const int4* dr = (const int4*)(g_d2q + (size_t)row * COMPS);

    int4 v[8];
    int lmin = 0x7fffffff;
    #pragma unroll
    for (int i = 0; i < 8; i++) {
        v[i] = dr[t + i * 256];
        const int* u = (const int*)&v[i];
        #pragma unroll
        for (int j = 0; j < 4; j++) {
            int lo = (int)(short)(u[j] & 0xFFFF);
            int hi = u[j] >> 16;
            lmin = min(lmin, min(lo, hi));
        }
    }
    red[t] = lmin;
    __syncthreads();
    for (int s = 128; s; s >>= 1) {
        if (t < s) red[t] = min(red[t], red[t + s]);
        __syncthreads();
    }
    int thr = red[0] + MARGIN_Q;
    if (t == 0) cnt = 0;
    __syncthreads();
    #pragma unroll
    for (int i = 0; i < 8; i++) {
        const int* u = (const int*)&v[i];
        #pragma unroll
        for (int j = 0; j < 4; j++) {
            int base = ((t + i * 256) * 4 + j) * 2;
            int lo = (int)(short)(u[j] & 0xFFFF);
            int hi = u[j] >> 16;
            if (lo <= thr) { int p = atomicAdd(&cnt, 1); if (p < 128) cand[p] = base; }
            if (hi <= thr) { int p = atomicAdd(&cnt, 1); if (p < 128) cand[p] = base + 1; }
        }
    }
    __syncthreads();
    int n = min(cnt, 128);
    if (t < 32) {
        const float* xr = X + (size_t)row * DIM;
        float bv = 3.4e38f; int bi = 0x7fffffff;
        for (int k = 0; k < n; k++) {
            int c = cand[k];
            const float* wr = W + (size_t)c * DIM;
            float s = 0.f;
            #pragma unroll
            for (int m = 0; m < 24; m++)
                s = fmaf(xr[t + m * 32], wr[t + m * 32], s);
            #pragma unroll
            for (int o = 16; o; o >>= 1) s += __shfl_xor_sync(0xffffffffu, s, o);
            float d2 = g_wn[c] - 2.f * s;
            if (d2 < bv || (d2 == bv && c < bi)) { bv = d2; bi = c; }
        }
        if (t == 0) g_bmu[row] = bi;
    }
}

__global__ void scatter_kernel(const float* __restrict__ X) {
    int b = blockIdx.x;
    int u = g_bmu[b];
    const float* xr = X + (size_t)b * DIM;
    float* tr = g_T + (size_t)u * DIM;
    for (int d = threadIdx.x; d < DIM; d += blockDim.x)
        atomicAdd(&tr[d], xr[d]);
    if (threadIdx.x == 0) atomicAdd(&g_cnt[u], 1.f);
}

// ---------------- separable Gaussian conv (128-matmul), in place ----------
__global__ __launch_bounds__(256) void conv_kernel(int rstride) {
    __shared__ float Ts[16][64];
    __shared__ float Gs[16][128];
    int t = threadIdx.x;
    size_t base = (size_t)blockIdx.y * (GRD * DIM) + (size_t)blockIdx.x * 64;
    int cg = t & 15, rg = t >> 4;
    int lk = t >> 4, lc = (t & 15) * 4, gi = (t & 15) * 8;

    float acc[8][4];
    #pragma unroll
    for (int r = 0; r < 8; r++)
        #pragma unroll
        for (int c = 0; c < 4; c++) acc[r][c] = 0.f;

    for (int k0 = 0; k0 < GRD; k0 += 16) {
        if (k0) __syncthreads();
        *(float4*)&Ts[lk][lc]     = *(const float4*)&g_T[base + (size_t)(k0 + lk) * rstride + lc];
        *(float4*)&Gs[lk][gi]     = *(const float4*)&g_G[(k0 + lk) * GRD + gi];
        *(float4*)&Gs[lk][gi + 4] = *(const float4*)&g_G[(k0 + lk) * GRD + gi + 4];
        __syncthreads();
        #pragma unroll
        for (int k = 0; k < 16; k++) {
            float4 tv = *(const float4*)&Ts[k][cg * 4];
            float tc[4] = {tv.x, tv.y, tv.z, tv.w};
            #pragma unroll
            for (int r = 0; r < 8; r++) {
                float g = Gs[k][rg * 8 + r];
                #pragma unroll
                for (int c = 0; c < 4; c++)
                    acc[r][c] = fmaf(g, tc[c], acc[r][c]);
            }
        }
    }
    #pragma unroll
    for (int r = 0; r < 8; r++) {
        float4 o = make_float4(acc[r][0], acc[r][1], acc[r][2], acc[r][3]);
        *(float4*)&g_T[base + (size_t)(rg * 8 + r) * rstride + cg * 4] = o;
    }
}

__global__ void convs1_kernel() {
    int ip = blockIdx.x, j = threadIdx.x;
    float s = 0.f;
    for (int i = 0; i < GRD; i++)
        s = fmaf(g_G[ip * GRD + i], g_cnt[i * GRD + j], s);
    g_s1[ip * GRD + j] = s;
}
__global__ void convs2_kernel() {
    int i = blockIdx.x, jp = threadIdx.x;
    float s = 0.f;
    for (int j = 0; j < GRD; j++)
        s = fmaf(g_G[j * GRD + jp], g_s1[i * GRD + j], s);
    g_s[i * GRD + jp] = s;
}

__global__ void final_kernel(const float* __restrict__ W, float* __restrict__ out,
                             const int* __restrict__ itp) {
    float decay = 1.f - (float)(*itp) / 1000.f;
    float alpha = 0.3f * decay;
    int idx = blockIdx.x * blockDim.x + threadIdx.x;
    int i4 = idx * 4;
    if (i4 >= COMPS * DIM) return;
    int c = i4 / DIM;
    float m = 1.f - alpha * g_s[c];
    float4 w = *(const float4*)(W + i4);
    float4 v = *(const float4*)(g_T + i4);
    float4 o = make_float4(w.x * m + alpha * v.x, w.y * m + alpha * v.y,
                           w.z * m + alpha * v.z, w.w * m + alpha * v.w);
    *(float4*)(out + i4) = o;
}

// ---------------- launch ----------------
extern "C" void kernel_launch(void* const* d_in, const int* in_sizes, int n_in,
                              void* d_out, int out_size) {
    const float* X   = (const float*)d_in[0];
    const float* W   = (const float*)d_in[1];
    const int*   itp = (const int*)d_in[2];
    float* out = (float*)d_out;

    cudaFuncSetAttribute(bmu_combo_kernel, cudaFuncAttributeMaxDynamicSharedMemorySize, QSMEM);

    float *tPtr, *cntPtr;
    cudaGetSymbolAddress((void**)&tPtr, g_T);
    cudaGetSymbolAddress((void**)&cntPtr, g_cnt);

    absmax2_kernel<<<2048, 256>>>(X, W);                          // 0
    quantX_kernel<<<(XN4 + 255) / 256, 256>>>(X);                 // 1
    quantW_wnorm_kernel<<<COMPS / 8, 256>>>(W);                   // 2
    bmu_combo_kernel<<<TOT_CTAS, 256, QSMEM>>>(X, W);             // 3  (ncu slot 3)
    cudaMemsetAsync(tPtr, 0, (size_t)COMPS * DIM * sizeof(float));
    cudaMemsetAsync(cntPtr, 0, COMPS * sizeof(float));
    gmat_kernel<<<GRD, GRD>>>(itp);
    bmu_scan_kernel<<<BSZ, 256>>>(X, W);
    scatter_kernel<<<BSZ, 256>>>(X);
    conv_kernel<<<dim3(GRD * DIM / 64, 1), 256>>>(GRD * DIM);
    conv_kernel<<<dim3(DIM / 64, GRD), 256>>>(DIM);
    convs1_kernel<<<GRD, GRD>>>();
    convs2_kernel<<<GRD, GRD>>>();
    final_kernel<<<(COMPS * DIM / 4 + 255) / 256, 256>>>(W, out, itp);
}

// round 9
// speedup vs baseline: 1.3210x; 1.3210x over previous
#include <cuda_runtime.h>
#include <math.h>
#include <cstdint>

#define BSZ   4096
#define DIM   768
#define COMPS 16384
#define GRD   128

// ---------------- device scratch ----------------
__device__ float g_T[COMPS * DIM];
__device__ float g_wn[COMPS];
__device__ float g_cnt[COMPS];
__device__ float g_s1[COMPS];
__device__ float g_s[COMPS];
__device__ float g_G[GRD * GRD];
__device__ int   g_bmu[BSZ];
__device__ unsigned g_maxX, g_maxW;
__device__ __align__(16) signed char g_Xq[BSZ * DIM];
__device__ __align__(16) signed char g_Wq[COMPS * DIM];
__device__ __align__(16) short g_d2q[(size_t)BSZ * COMPS];   // approx d2 * 4

// ---------------- helpers ----------------
__device__ __forceinline__ uint32_t smem_to_u32(const void* p) {
    uint32_t a;
    asm("{ .reg .u64 t; cvta.to.shared.u64 t, %1; cvt.u32.u64 %0, t; }" : "=r"(a) : "l"(p));
    return a;
}
__device__ __forceinline__ void cp_async16(uint32_t dst, const void* src) {
    asm volatile("cp.async.cg.shared.global [%0], [%1], 16;" :: "r"(dst), "l"(src));
}
__device__ __forceinline__ uint32_t lds32(uint32_t a) {
    uint32_t v;
    asm volatile("ld.shared.b32 %0, [%1];" : "=r"(v) : "r"(a));
    return v;
}
__device__ __forceinline__ void mma_s8(int* d, const uint32_t* a, const uint32_t* b) {
    asm volatile(
        "mma.sync.aligned.m16n8k32.row.col.s32.s8.s8.s32 "
        "{%0,%1,%2,%3}, {%4,%5,%6,%7}, {%8,%9}, {%0,%1,%2,%3};"
        : "+r"(d[0]), "+r"(d[1]), "+r"(d[2]), "+r"(d[3])
        : "r"(a[0]), "r"(a[1]), "r"(a[2]), "r"(a[3]), "r"(b[0]), "r"(b[1]));
}

// ---------------- pre kernels ----------------
#define XN4 (BSZ * DIM / 4)
#define WN4 (COMPS * DIM / 4)
__global__ void absmax2_kernel(const float* __restrict__ X, const float* __restrict__ W) {
    __shared__ float rx[256], rw[256];
    float mx = 0.f, mw = 0.f;
    int stride = gridDim.x * blockDim.x;
    for (int i = blockIdx.x * blockDim.x + threadIdx.x; i < XN4 + WN4; i += stride) {
        float4 v = (i < XN4) ? *(const float4*)(X + (size_t)i * 4)
                             : *(const float4*)(W + (size_t)(i - XN4) * 4);
        float m = fmaxf(fmaxf(fabsf(v.x), fabsf(v.y)), fmaxf(fabsf(v.z), fabsf(v.w)));
        if (i < XN4) mx = fmaxf(mx, m); else mw = fmaxf(mw, m);
    }
    rx[threadIdx.x] = mx; rw[threadIdx.x] = mw;
    __syncthreads();
    for (int s = 128; s; s >>= 1) {
        if (threadIdx.x < s) {
            rx[threadIdx.x] = fmaxf(rx[threadIdx.x], rx[threadIdx.x + s]);
            rw[threadIdx.x] = fmaxf(rw[threadIdx.x], rw[threadIdx.x + s]);
        }
        __syncthreads();
    }
    if (threadIdx.x == 0) {
        atomicMax(&g_maxX, __float_as_uint(rx[0]));
        atomicMax(&g_maxW, __float_as_uint(rw[0]));
    }
}

__global__ void quantX_kernel(const float* __restrict__ src) {
    int i = blockIdx.x * blockDim.x + threadIdx.x;
    if (i >= XN4) return;
    float inv = 127.f / __uint_as_float(g_maxX);
    float4 v = *(const float4*)(src + (size_t)i * 4);
    float x[4] = {v.x, v.y, v.z, v.w};
    unsigned pk = 0;
    #pragma unroll
    for (int k = 0; k < 4; k++) {
        int q = __float2int_rn(x[k] * inv);
        q = max(-127, min(127, q));
        pk |= ((unsigned)(q & 0xFF)) << (k * 8);
    }
    *(unsigned*)(g_Xq + (size_t)i * 4) = pk;
}

__global__ void quantW_wnorm_kernel(const float* __restrict__ W) {
    int row = blockIdx.x * 8 + (threadIdx.x >> 5);
    int lane = threadIdx.x & 31;
    float inv = 127.f / __uint_as_float(g_maxW);
    const float* wr = W + (size_t)row * DIM;
    float s = 0.f;
    #pragma unroll
    for (int k = 0; k < 6; k++) {
        int e = lane * 4 + k * 128;
        float4 v = *(const float4*)(wr + e);
        float x[4] = {v.x, v.y, v.z, v.w};
        unsigned pk = 0;
        #pragma unroll
        for (int j = 0; j < 4; j++) {
            s = fmaf(x[j], x[j], s);
            int q = __float2int_rn(x[j] * inv);
            q = max(-127, min(127, q));
            pk |= ((unsigned)(q & 0xFF)) << (j * 8);
        }
        *(unsigned*)(g_Wq + (size_t)row * DIM + e) = pk;
    }
    #pragma unroll
    for (int o = 16; o; o >>= 1) s += __shfl_xor_sync(0xffffffffu, s, o);
    if (lane == 0) g_wn[row] = s;
}

__global__ void gmat_kernel(const int* __restrict__ itp) {
    float decay = 1.f - (float)(*itp) / 1000.f;
    float sig = 64.f * decay;
    int a = blockIdx.x, b = threadIdx.x;
    float d = (float)(a - b);
    g_G[a * GRD + b] = expf(-(d * d) / (sig * sig));
}

// ---------------- int8 BMU GEMM: 128x128 tiles, 2 CTAs/SM, 4 stages ------
#define QPITCH  48
#define QT_TILE 6144
#define QSTAGE  12288            // A + B per stage
#define QWNS    (4 * QSTAGE)     // 49152
#define QSMEM   (QWNS + 512)     // 49664

__global__ __launch_bounds__(256, 2) void bmu_q_kernel() {
    extern __shared__ char sm[];
    const uint32_t sb = smem_to_u32(sm);
    const int t = threadIdx.x, lane = t & 31, w = t >> 5;
    const int wm = w >> 2, wn_ = w & 3;
    const int arow = lane >> 2, ac4 = (lane & 3) * 4;
    const int bx = blockIdx.x, by = blockIdx.y;
    const int rowX = by * 128, rowW = bx * 128;

    float* wns = (float*)(sm + QWNS);
    if (t < 128) wns[t] = g_wn[rowW + t];

    int acc[4][4][4];
    #pragma unroll
    for (int mi = 0; mi < 4; mi++)
        #pragma unroll
        for (int ni = 0; ni < 4; ni++)
            #pragma unroll
            for (int k = 0; k < 4; k++) acc[mi][ni][k] = 0;

    auto load_stage = [&](int s, int c) {
        uint32_t base = sb + s * QSTAGE;
        int r = t >> 1, g = t & 1;
        cp_async16(base + r * QPITCH + g * 16,
                   g_Xq + (size_t)(rowX + r) * DIM + c * 32 + g * 16);
        cp_async16(base + QT_TILE + r * QPITCH + g * 16,
                   g_Wq + (size_t)(rowW + r) * DIM + c * 32 + g * 16);
    };
    auto compute = [&](int s) {
        uint32_t Ah = sb + s * QSTAGE;
        uint32_t Bh = Ah + QT_TILE;
        uint32_t b[4][2];
        #pragma unroll
        for (int ni = 0; ni < 4; ni++) {
            uint32_t off = Bh + (uint32_t)((wn_ * 32 + ni * 8 + arow) * QPITCH + ac4);
            b[ni][0] = lds32(off); b[ni][1] = lds32(off + 16);
        }
        uint32_t a[4][4];
        #pragma unroll
        for (int mi = 0; mi < 4; mi++) {
            uint32_t off = Ah + (uint32_t)((wm * 64 + mi * 16 + arow) * QPITCH + ac4);
            a[mi][0] = lds32(off);      a[mi][1] = lds32(off + 8 * QPITCH);
            a[mi][2] = lds32(off + 16); a[mi][3] = lds32(off + 8 * QPITCH + 16);
        }
        #pragma unroll
        for (int mi = 0; mi < 4; mi++)
            #pragma unroll
            for (int ni = 0; ni < 4; ni++) mma_s8(acc[mi][ni], a[mi], b[ni]);
    };

    #pragma unroll
    for (int p = 0; p < 3; p++) { load_stage(p, p); asm volatile("cp.async.commit_group;"); }
    for (int c = 0; c < 24; c++) {
        asm volatile("cp.async.wait_group 2;");
        __syncthreads();
        if (c + 3 < 24) load_stage((c + 3) & 3, c + 3);
        asm volatile("cp.async.commit_group;");
        compute(c & 3);
    }

    // epilogue: d2 = wn - 2*sx*sw*dot, quantize *4 to int16, dump
    float twoss = 2.f * (__uint_as_float(g_maxX) / 127.f) * (__uint_as_float(g_maxW) / 127.f);
    #pragma unroll
    for (int mi = 0; mi < 4; mi++) {
        int r0 = rowX + wm * 64 + mi * 16 + arow;
        #pragma unroll
        for (int ni = 0; ni < 4; ni++) {
            int col0 = wn_ * 32 + ni * 8 + (lane & 3) * 2;
            float w0 = wns[col0], w1 = wns[col0 + 1];
            #pragma unroll
            for (int h = 0; h < 2; h++) {
                float d0 = (w0 - twoss * (float)acc[mi][ni][h * 2 + 0]) * 4.f;
                float d1 = (w1 - twoss * (float)acc[mi][ni][h * 2 + 1]) * 4.f;
                int q0 = __float2int_rn(fminf(fmaxf(d0, -32000.f), 32000.f));
                int q1 = __float2int_rn(fminf(fmaxf(d1, -32000.f), 32000.f));
                unsigned pk = (unsigned)(q0 & 0xFFFF) | ((unsigned)q1 << 16);
                *(unsigned*)(g_d2q + (size_t)(r0 + h * 8) * COMPS + rowW + col0) = pk;
            }
        }
    }
}

// ---------------- candidate rescue: min + margin scan + exact fp32 -------
#define MARGIN_Q 48
__global__ __launch_bounds__(256) void bmu_scan_kernel(const float* __restrict__ X,
                                                       const float* __restrict__ W) {
    __shared__ int red[256];
    __shared__ int cnt;
    __shared__ int cand[128];
    int row = blockIdx.x, t = threadIdx.x;
    const int4* dr = (const int4*)(g_d2q + (size_t)row * COMPS);

    int4 v[8];
    int lmin = 0x7fffffff;
    #pragma unroll
    for (int i = 0; i < 8; i++) {
        v[i] = dr[t + i * 256];
        const int* u = (const int*)&v[i];
        #pragma unroll
        for (int j = 0; j < 4; j++) {
            int lo = (int)(short)(u[j] & 0xFFFF);
            int hi = u[j] >> 16;
            lmin = min(lmin, min(lo, hi));
        }
    }
    red[t] = lmin;
    __syncthreads();
    for (int s = 128; s; s >>= 1) {
        if (t < s) red[t] = min(red[t], red[t + s]);
        __syncthreads();
    }
    int thr = red[0] + MARGIN_Q;
    if (t == 0) cnt = 0;
    __syncthreads();
    #pragma unroll
    for (int i = 0; i < 8; i++) {
        const int* u = (const int*)&v[i];
        #pragma unroll
        for (int j = 0; j < 4; j++) {
            int base = ((t + i * 256) * 4 + j) * 2;
            int lo = (int)(short)(u[j] & 0xFFFF);
            int hi = u[j] >> 16;
            if (lo <= thr) { int p = atomicAdd(&cnt, 1); if (p < 128) cand[p] = base; }
            if (hi <= thr) { int p = atomicAdd(&cnt, 1); if (p < 128) cand[p] = base + 1; }
        }
    }
    __syncthreads();
    int n = min(cnt, 128);
    if (t < 32) {
        const float* xr = X + (size_t)row * DIM;
        float bv = 3.4e38f; int bi = 0x7fffffff;
        for (int k = 0; k < n; k++) {
            int c = cand[k];
            const float* wr = W + (size_t)c * DIM;
            float s = 0.f;
            #pragma unroll
            for (int m = 0; m < 24; m++)
                s = fmaf(xr[t + m * 32], wr[t + m * 32], s);
            #pragma unroll
            for (int o = 16; o; o >>= 1) s += __shfl_xor_sync(0xffffffffu, s, o);
            float d2 = g_wn[c] - 2.f * s;
            if (d2 < bv || (d2 == bv && c < bi)) { bv = d2; bi = c; }
        }
        if (t == 0) g_bmu[row] = bi;
    }
}

__global__ void scatter_kernel(const float* __restrict__ X) {
    int b = blockIdx.x;
    int u = g_bmu[b];
    const float* xr = X + (size_t)b * DIM;
    float* tr = g_T + (size_t)u * DIM;
    for (int d = threadIdx.x; d < DIM; d += blockDim.x)
        atomicAdd(&tr[d], xr[d]);
    if (threadIdx.x == 0) atomicAdd(&g_cnt[u], 1.f);
}

// ---------------- separable Gaussian conv (128-matmul), in place ----------
__global__ __launch_bounds__(256) void conv_kernel(int rstride) {
    __shared__ float Ts[16][64];
    __shared__ float Gs[16][128];
    int t = threadIdx.x;
    size_t base = (size_t)blockIdx.y * (GRD * DIM) + (size_t)blockIdx.x * 64;
    int cg = t & 15, rg = t >> 4;
    int lk = t >> 4, lc = (t & 15) * 4, gi = (t & 15) * 8;

    float acc[8][4];
    #pragma unroll
    for (int r = 0; r < 8; r++)
        #pragma unroll
        for (int c = 0; c < 4; c++) acc[r][c] = 0.f;

    for (int k0 = 0; k0 < GRD; k0 += 16) {
        if (k0) __syncthreads();
        *(float4*)&Ts[lk][lc]     = *(const float4*)&g_T[base + (size_t)(k0 + lk) * rstride + lc];
        *(float4*)&Gs[lk][gi]     = *(const float4*)&g_G[(k0 + lk) * GRD + gi];
        *(float4*)&Gs[lk][gi + 4] = *(const float4*)&g_G[(k0 + lk) * GRD + gi + 4];
        __syncthreads();
        #pragma unroll
        for (int k = 0; k < 16; k++) {
            float4 tv = *(const float4*)&Ts[k][cg * 4];
            float tc[4] = {tv.x, tv.y, tv.z, tv.w};
            #pragma unroll
            for (int r = 0; r < 8; r++) {
                float g = Gs[k][rg * 8 + r];
                #pragma unroll
                for (int c = 0; c < 4; c++)
                    acc[r][c] = fmaf(g, tc[c], acc[r][c]);
            }
        }
    }
    #pragma unroll
    for (int r = 0; r < 8; r++) {
        float4 o = make_float4(acc[r][0], acc[r][1], acc[r][2], acc[r][3]);
        *(float4*)&g_T[base + (size_t)(rg * 8 + r) * rstride + cg * 4] = o;
    }
}

__global__ void convs1_kernel() {
    int ip = blockIdx.x, j = threadIdx.x;
    float s = 0.f;
    for (int i = 0; i < GRD; i++)
        s = fmaf(g_G[ip * GRD + i], g_cnt[i * GRD + j], s);
    g_s1[ip * GRD + j] = s;
}
__global__ void convs2_kernel() {
    int i = blockIdx.x, jp = threadIdx.x;
    float s = 0.f;
    for (int j = 0; j < GRD; j++)
        s = fmaf(g_G[j * GRD + jp], g_s1[i * GRD + j], s);
    g_s[i * GRD + jp] = s;
}

__global__ void final_kernel(const float* __restrict__ W, float* __restrict__ out,
                             const int* __restrict__ itp) {
    float decay = 1.f - (float)(*itp) / 1000.f;
    float alpha = 0.3f * decay;
    int idx = blockIdx.x * blockDim.x + threadIdx.x;
    int i4 = idx * 4;
    if (i4 >= COMPS * DIM) return;
    int c = i4 / DIM;
    float m = 1.f - alpha * g_s[c];
    float4 w = *(const float4*)(W + i4);
    float4 v = *(const float4*)(g_T + i4);
    float4 o = make_float4(w.x * m + alpha * v.x, w.y * m + alpha * v.y,
                           w.z * m + alpha * v.z, w.w * m + alpha * v.w);
    *(float4*)(out + i4) = o;
}

// ---------------- launch ----------------
extern "C" void kernel_launch(void* const* d_in, const int* in_sizes, int n_in,
                              void* d_out, int out_size) {
    const float* X   = (const float*)d_in[0];
    const float* W   = (const float*)d_in[1];
    const int*   itp = (const int*)d_in[2];
    float* out = (float*)d_out;

    cudaFuncSetAttribute(bmu_q_kernel, cudaFuncAttributeMaxDynamicSharedMemorySize, QSMEM);

    float *tPtr, *cntPtr;
    cudaGetSymbolAddress((void**)&tPtr, g_T);
    cudaGetSymbolAddress((void**)&cntPtr, g_cnt);

    absmax2_kernel<<<2048, 256>>>(X, W);                          // 0
    quantX_kernel<<<(XN4 + 255) / 256, 256>>>(X);                 // 1
    quantW_wnorm_kernel<<<COMPS / 8, 256>>>(W);                   // 2
    bmu_q_kernel<<<dim3(COMPS / 128, BSZ / 128), 256, QSMEM>>>(); // 3  (ncu slot 3)
    cudaMemsetAsync(tPtr, 0, (size_t)COMPS * DIM * sizeof(float));
    cudaMemsetAsync(cntPtr, 0, COMPS * sizeof(float));
    gmat_kernel<<<GRD, GRD>>>(itp);
    bmu_scan_kernel<<<BSZ, 256>>>(X, W);
    scatter_kernel<<<BSZ, 256>>>(X);
    conv_kernel<<<dim3(GRD * DIM / 64, 1), 256>>>(GRD * DIM);
    conv_kernel<<<dim3(DIM / 64, GRD), 256>>>(DIM);
    convs1_kernel<<<GRD, GRD>>>();
    convs2_kernel<<<GRD, GRD>>>();
    final_kernel<<<(COMPS * DIM / 4 + 255) / 256, 256>>>(W, out, itp);
}

// round 10
// speedup vs baseline: 1.3716x; 1.0383x over previous
#include <cuda_runtime.h>
#include <math.h>
#include <cstdint>

#define BSZ   4096
#define DIM   768
#define COMPS 16384
#define GRD   128

// ---------------- device scratch ----------------
__device__ float g_T[COMPS * DIM];
__device__ float g_wn[COMPS];
__device__ float g_cnt[COMPS];
__device__ float g_s1[COMPS];
__device__ float g_s[COMPS];
__device__ float g_G[GRD * GRD];
__device__ int   g_bmu[BSZ];
__device__ unsigned g_maxX, g_maxW;
__device__ __align__(16) signed char g_Xq[BSZ * DIM];
__device__ __align__(16) signed char g_Wq[COMPS * DIM];
__device__ __align__(16) float4 g_top2[(size_t)BSZ * 128];   // per (row, coltile): v0,i0,v1,i1

// ---------------- helpers ----------------
__device__ __forceinline__ uint32_t smem_to_u32(const void* p) {
    uint32_t a;
    asm("{ .reg .u64 t; cvta.to.shared.u64 t, %1; cvt.u32.u64 %0, t; }" : "=r"(a) : "l"(p));
    return a;
}
__device__ __forceinline__ void cp_async16(uint32_t dst, const void* src) {
    asm volatile("cp.async.cg.shared.global [%0], [%1], 16;" :: "r"(dst), "l"(src));
}
__device__ __forceinline__ uint32_t lds32(uint32_t a) {
    uint32_t v;
    asm volatile("ld.shared.b32 %0, [%1];" : "=r"(v) : "r"(a));
    return v;
}
__device__ __forceinline__ void mma_s8(int* d, const uint32_t* a, const uint32_t* b) {
    asm volatile(
        "mma.sync.aligned.m16n8k32.row.col.s32.s8.s8.s32 "
        "{%0,%1,%2,%3}, {%4,%5,%6,%7}, {%8,%9}, {%0,%1,%2,%3};"
        : "+r"(d[0]), "+r"(d[1]), "+r"(d[2]), "+r"(d[3])
        : "r"(a[0]), "r"(a[1]), "r"(a[2]), "r"(a[3]), "r"(b[0]), "r"(b[1]));
}
__device__ __forceinline__ unsigned long long pack2(float lo, float hi) {
    unsigned long long r;
    asm("mov.b64 %0, {%1, %2};" : "=l"(r) : "r"(__float_as_uint(lo)), "r"(__float_as_uint(hi)));
    return r;
}
__device__ __forceinline__ void ffma2(unsigned long long& d, unsigned long long a,
                                      unsigned long long b) {
    asm("fma.rn.f32x2 %0, %1, %2, %0;" : "+l"(d) : "l"(a), "l"(b));
}
__device__ __forceinline__ void unpack2(unsigned long long p, float& lo, float& hi) {
    unsigned l, h;
    asm("mov.b64 {%0, %1}, %2;" : "=r"(l), "=r"(h) : "l"(p));
    lo = __uint_as_float(l); hi = __uint_as_float(h);
}

// ---------------- pre kernels ----------------
#define XN4 (BSZ * DIM / 4)
#define WN4 (COMPS * DIM / 4)
__global__ void absmax2_kernel(const float* __restrict__ X, const float* __restrict__ W) {
    __shared__ float rx[256], rw[256];
    float mx = 0.f, mw = 0.f;
    int stride = gridDim.x * blockDim.x;
    for (int i = blockIdx.x * blockDim.x + threadIdx.x; i < XN4 + WN4; i += stride) {
        float4 v = (i < XN4) ? *(const float4*)(X + (size_t)i * 4)
                             : *(const float4*)(W + (size_t)(i - XN4) * 4);
        float m = fmaxf(fmaxf(fabsf(v.x), fabsf(v.y)), fmaxf(fabsf(v.z), fabsf(v.w)));
        if (i < XN4) mx = fmaxf(mx, m); else mw = fmaxf(mw, m);
    }
    rx[threadIdx.x] = mx; rw[threadIdx.x] = mw;
    __syncthreads();
    for (int s = 128; s; s >>= 1) {
        if (threadIdx.x < s) {
            rx[threadIdx.x] = fmaxf(rx[threadIdx.x], rx[threadIdx.x + s]);
            rw[threadIdx.x] = fmaxf(rw[threadIdx.x], rw[threadIdx.x + s]);
        }
        __syncthreads();
    }
    if (threadIdx.x == 0) {
        atomicMax(&g_maxX, __float_as_uint(rx[0]));
        atomicMax(&g_maxW, __float_as_uint(rw[0]));
    }
}

__global__ void quantX_kernel(const float* __restrict__ src) {
    int i = blockIdx.x * blockDim.x + threadIdx.x;
    if (i >= XN4) return;
    float inv = 127.f / __uint_as_float(g_maxX);
    float4 v = *(const float4*)(src + (size_t)i * 4);
    float x[4] = {v.x, v.y, v.z, v.w};
    unsigned pk = 0;
    #pragma unroll
    for (int k = 0; k < 4; k++) {
        int q = __float2int_rn(x[k] * inv);
        q = max(-127, min(127, q));
        pk |= ((unsigned)(q & 0xFF)) << (k * 8);
    }
    *(unsigned*)(g_Xq + (size_t)i * 4) = pk;
}

__global__ void quantW_wnorm_kernel(const float* __restrict__ W) {
    int row = blockIdx.x * 8 + (threadIdx.x >> 5);
    int lane = threadIdx.x & 31;
    float inv = 127.f / __uint_as_float(g_maxW);
    const float* wr = W + (size_t)row * DIM;
    float s = 0.f;
    #pragma unroll
    for (int k = 0; k < 6; k++) {
        int e = lane * 4 + k * 128;
        float4 v = *(const float4*)(wr + e);
        float x[4] = {v.x, v.y, v.z, v.w};
        unsigned pk = 0;
        #pragma unroll
        for (int j = 0; j < 4; j++) {
            s = fmaf(x[j], x[j], s);
            int q = __float2int_rn(x[j] * inv);
            q = max(-127, min(127, q));
            pk |= ((unsigned)(q & 0xFF)) << (j * 8);
        }
        *(unsigned*)(g_Wq + (size_t)row * DIM + e) = pk;
    }
    #pragma unroll
    for (int o = 16; o; o >>= 1) s += __shfl_xor_sync(0xffffffffu, s, o);
    if (lane == 0) g_wn[row] = s;
}

__global__ void gmat_kernel(const int* __restrict__ itp) {
    float decay = 1.f - (float)(*itp) / 1000.f;
    float sig = 64.f * decay;
    int a = blockIdx.x, b = threadIdx.x;
    float d = (float)(a - b);
    g_G[a * GRD + b] = expf(-(d * d) / (sig * sig));
}

// ---------------- int8 BMU GEMM: 128x128 tiles, 2 CTAs/SM, 4 stages ------
// epilogue: per-row top-2 over this tile -> g_top2 (8 MB total)
#define QPITCH  48
#define QT_TILE 6144
#define QSTAGE  12288
#define QWNS    (4 * QSTAGE)     // 49152
#define QSMEM   (QWNS + 512)     // 49664

#define INS2(v, i)                                            \
    do {                                                      \
        float _v = (v); int _i = (i);                         \
        if (_v < v0) { v1 = v0; i1 = i0; v0 = _v; i0 = _i; }  \
        else if (_v < v1) { v1 = _v; i1 = _i; }               \
    } while (0)

__global__ __launch_bounds__(256, 2) void bmu_q_kernel() {
    extern __shared__ char sm[];
    const uint32_t sb = smem_to_u32(sm);
    const int t = threadIdx.x, lane = t & 31, w = t >> 5;
    const int wm = w >> 2, wn_ = w & 3;
    const int arow = lane >> 2, ac4 = (lane & 3) * 4;
    const int bx = blockIdx.x, by = blockIdx.y;
    const int rowX = by * 128, rowW = bx * 128;

    float* wns = (float*)(sm + QWNS);
    if (t < 128) wns[t] = g_wn[rowW + t];

    int acc[4][4][4];
    #pragma unroll
    for (int mi = 0; mi < 4; mi++)
        #pragma unroll
        for (int ni = 0; ni < 4; ni++)
            #pragma unroll
            for (int k = 0; k < 4; k++) acc[mi][ni][k] = 0;

    auto load_stage = [&](int s, int c) {
        uint32_t base = sb + s * QSTAGE;
        int r = t >> 1, g = t & 1;
        cp_async16(base + r * QPITCH + g * 16,
                   g_Xq + (size_t)(rowX + r) * DIM + c * 32 + g * 16);
        cp_async16(base + QT_TILE + r * QPITCH + g * 16,
                   g_Wq + (size_t)(rowW + r) * DIM + c * 32 + g * 16);
    };
    auto compute = [&](int s) {
        uint32_t Ah = sb + s * QSTAGE;
        uint32_t Bh = Ah + QT_TILE;
        uint32_t b[4][2];
        #pragma unroll
        for (int ni = 0; ni < 4; ni++) {
            uint32_t off = Bh + (uint32_t)((wn_ * 32 + ni * 8 + arow) * QPITCH + ac4);
            b[ni][0] = lds32(off); b[ni][1] = lds32(off + 16);
        }
        uint32_t a[4][4];
        #pragma unroll
        for (int mi = 0; mi < 4; mi++) {
            uint32_t off = Ah + (uint32_t)((wm * 64 + mi * 16 + arow) * QPITCH + ac4);
            a[mi][0] = lds32(off);      a[mi][1] = lds32(off + 8 * QPITCH);
            a[mi][2] = lds32(off + 16); a[mi][3] = lds32(off + 8 * QPITCH + 16);
        }
        #pragma unroll
        for (int mi = 0; mi < 4; mi++)
            #pragma unroll
            for (int ni = 0; ni < 4; ni++) mma_s8(acc[mi][ni], a[mi], b[ni]);
    };

    #pragma unroll
    for (int p = 0; p < 3; p++) { load_stage(p, p); asm volatile("cp.async.commit_group;"); }
    for (int c = 0; c < 24; c++) {
        asm volatile("cp.async.wait_group 2;");
        __syncthreads();
        if (c + 3 < 24) load_stage((c + 3) & 3, c + 3);
        asm volatile("cp.async.commit_group;");
        compute(c & 3);
    }

    // ---- epilogue: per-row top-2 of d2 = wn - 2*sx*sw*dot over 128 cols ----
    __syncthreads();                       // stage smem free for reuse
    float4* top2s = (float4*)sm;           // [128 rows][4 warps]
    float twoss = 2.f * (__uint_as_float(g_maxX) / 127.f) * (__uint_as_float(g_maxW) / 127.f);

    #pragma unroll
    for (int mi = 0; mi < 4; mi++) {
        #pragma unroll
        for (int h = 0; h < 2; h++) {
            float v0 = 3.4e38f, v1 = 3.4e38f;
            int i0 = 0x7fffffff, i1 = 0x7fffffff;
            #pragma unroll
            for (int ni = 0; ni < 4; ni++) {
                #pragma unroll
                for (int cc = 0; cc < 2; cc++) {
                    int col = wn_ * 32 + ni * 8 + (lane & 3) * 2 + cc;
                    float d2 = wns[col] - twoss * (float)acc[mi][ni][h * 2 + cc];
                    INS2(d2, rowW + col);
                }
            }
            #pragma unroll
            for (int o = 1; o < 4; o <<= 1) {
                float ov0 = __shfl_xor_sync(0xffffffffu, v0, o);
                int   oi0 = __shfl_xor_sync(0xffffffffu, i0, o);
                float ov1 = __shfl_xor_sync(0xffffffffu, v1, o);
                int   oi1 = __shfl_xor_sync(0xffffffffu, i1, o);
                INS2(ov0, oi0);
                INS2(ov1, oi1);
            }
            if ((lane & 3) == 0) {
                int rr = wm * 64 + mi * 16 + h * 8 + arow;
                top2s[rr * 4 + wn_] = make_float4(v0, __int_as_float(i0),
                                                  v1, __int_as_float(i1));
            }
        }
    }
    __syncthreads();
    if (t < 128) {
        float4 a0 = top2s[t * 4 + 0];
        float v0 = a0.x, v1 = a0.z;
        int i0 = __float_as_int(a0.y), i1 = __float_as_int(a0.w);
        #pragma unroll
        for (int j = 1; j < 4; j++) {
            float4 aj = top2s[t * 4 + j];
            INS2(aj.x, __float_as_int(aj.y));
            INS2(aj.z, __float_as_int(aj.w));
        }
        g_top2[(size_t)(rowX + t) * 128 + bx] =
            make_float4(v0, __int_as_float(i0), v1, __int_as_float(i1));
    }
}

// ---------------- candidate rescue: min + margin over top-2 + exact fp32 --
#define MARGIN_F 12.0f
__global__ __launch_bounds__(128) void bmu_scan_kernel(const float* __restrict__ X,
                                                       const float* __restrict__ W) {
    __shared__ float red[128];
    __shared__ int cnt;
    __shared__ int cand[128];
    int row = blockIdx.x, t = threadIdx.x;
    float4 e = g_top2[(size_t)row * 128 + t];

    red[t] = e.x;
    __syncthreads();
    for (int s = 64; s; s >>= 1) {
        if (t < s) red[t] = fminf(red[t], red[t + s]);
        __syncthreads();
    }
    float thr = red[0] + MARGIN_F;
    if (t == 0) cnt = 0;
    __syncthreads();
    if (e.x <= thr) { int p = atomicAdd(&cnt, 1); if (p < 128) cand[p] = __float_as_int(e.y); }
    if (e.z <= thr) { int p = atomicAdd(&cnt, 1); if (p < 128) cand[p] = __float_as_int(e.w); }
    __syncthreads();
    int n = min(cnt, 128);
    if (t < 32) {
        const float* xr = X + (size_t)row * DIM;
        float bv = 3.4e38f; int bi = 0x7fffffff;
        for (int k = 0; k < n; k++) {
            int c = cand[k];
            const float* wr = W + (size_t)c * DIM;
            float s = 0.f;
            #pragma unroll
            for (int m = 0; m < 24; m++)
                s = fmaf(xr[t + m * 32], wr[t + m * 32], s);
            #pragma unroll
            for (int o = 16; o; o >>= 1) s += __shfl_xor_sync(0xffffffffu, s, o);
            float d2 = g_wn[c] - 2.f * s;
            if (d2 < bv || (d2 == bv && c < bi)) { bv = d2; bi = c; }
        }
        if (t == 0) g_bmu[row] = bi;
    }
}

__global__ void scatter_kernel(const float* __restrict__ X) {
    int b = blockIdx.x;
    int u = g_bmu[b];
    const float* xr = X + (size_t)b * DIM;
    float* tr = g_T + (size_t)u * DIM;
    for (int d = threadIdx.x; d < DIM; d += blockDim.x)
        atomicAdd(&tr[d], xr[d]);
    if (threadIdx.x == 0) atomicAdd(&g_cnt[u], 1.f);
}

// ---------------- separable Gaussian conv via packed f32x2, in place ------
__global__ __launch_bounds__(256) void conv_kernel(int rstride) {
    __shared__ float Ts[16][64];
    __shared__ float Gs[16][128];
    int t = threadIdx.x;
    size_t base = (size_t)blockIdx.y * (GRD * DIM) + (size_t)blockIdx.x * 64;
    int cg = t & 15, rg = t >> 4;
    int lk = t >> 4, lc = (t & 15) * 4, gi = (t & 15) * 8;

    unsigned long long acc2[8][2];
    #pragma unroll
    for (int r = 0; r < 8; r++) { acc2[r][0] = 0ull; acc2[r][1] = 0ull; }

    for (int k0 = 0; k0 < GRD; k0 += 16) {
        if (k0) __syncthreads();
        *(float4*)&Ts[lk][lc]     = *(const float4*)&g_T[base + (size_t)(k0 + lk) * rstride + lc];
        *(float4*)&Gs[lk][gi]     = *(const float4*)&g_G[(k0 + lk) * GRD + gi];
        *(float4*)&Gs[lk][gi + 4] = *(const float4*)&g_G[(k0 + lk) * GRD + gi + 4];
        __syncthreads();
        #pragma unroll
        for (int k = 0; k < 16; k++) {
            float4 tv = *(const float4*)&Ts[k][cg * 4];
            unsigned long long b0 = pack2(tv.x, tv.y);
            unsigned long long b1 = pack2(tv.z, tv.w);
            #pragma unroll
            for (int r = 0; r < 8; r++) {
                float g = Gs[k][rg * 8 + r];
                unsigned long long gp = pack2(g, g);
                ffma2(acc2[r][0], gp, b0);
                ffma2(acc2[r][1], gp, b1);
            }
        }
    }
    #pragma unroll
    for (int r = 0; r < 8; r++) {
        float4 o;
        unpack2(acc2[r][0], o.x, o.y);
        unpack2(acc2[r][1], o.z, o.w);
        *(float4*)&g_T[base + (size_t)(rg * 8 + r) * rstride + cg * 4] = o;
    }
}

__global__ void convs1_kernel() {
    int ip = blockIdx.x, j = threadIdx.x;
    float s = 0.f;
    for (int i = 0; i < GRD; i++)
        s = fmaf(g_G[ip * GRD + i], g_cnt[i * GRD + j], s);
    g_s1[ip * GRD + j] = s;
}
__global__ void convs2_kernel() {
    int i = blockIdx.x, jp = threadIdx.x;
    float s = 0.f;
    for (int j = 0; j < GRD; j++)
        s = fmaf(g_G[j * GRD + jp], g_s1[i * GRD + j], s);
    g_s[i * GRD + jp] = s;
}

__global__ void final_kernel(const float* __restrict__ W, float* __restrict__ out,
                             const int* __restrict__ itp) {
    float decay = 1.f - (float)(*itp) / 1000.f;
    float alpha = 0.3f * decay;
    int idx = blockIdx.x * blockDim.x + threadIdx.x;
    int i4 = idx * 4;
    if (i4 >= COMPS * DIM) return;
    int c = i4 / DIM;
    float m = 1.f - alpha * g_s[c];
    float4 w = *(const float4*)(W + i4);
    float4 v = *(const float4*)(g_T + i4);
    float4 o = make_float4(w.x * m + alpha * v.x, w.y * m + alpha * v.y,
                           w.z * m + alpha * v.z, w.w * m + alpha * v.w);
    *(float4*)(out + i4) = o;
}

// ---------------- launch ----------------
extern "C" void kernel_launch(void* const* d_in, const int* in_sizes, int n_in,
                              void* d_out, int out_size) {
    const float* X   = (const float*)d_in[0];
    const float* W   = (const float*)d_in[1];
    const int*   itp = (const int*)d_in[2];
    float* out = (float*)d_out;

    cudaFuncSetAttribute(bmu_q_kernel, cudaFuncAttributeMaxDynamicSharedMemorySize, QSMEM);

    float *tPtr, *cntPtr;
    cudaGetSymbolAddress((void**)&tPtr, g_T);
    cudaGetSymbolAddress((void**)&cntPtr, g_cnt);

    absmax2_kernel<<<2048, 256>>>(X, W);                          // 0
    quantX_kernel<<<(XN4 + 255) / 256, 256>>>(X);                 // 1
    quantW_wnorm_kernel<<<COMPS / 8, 256>>>(W);                   // 2
    bmu_q_kernel<<<dim3(COMPS / 128, BSZ / 128), 256, QSMEM>>>(); // 3  (ncu slot 3)
    cudaMemsetAsync(tPtr, 0, (size_t)COMPS * DIM * sizeof(float));
    cudaMemsetAsync(cntPtr, 0, COMPS * sizeof(float));
    gmat_kernel<<<GRD, GRD>>>(itp);
    bmu_scan_kernel<<<BSZ, 128>>>(X, W);
    scatter_kernel<<<BSZ, 256>>>(X);
    conv_kernel<<<dim3(GRD * DIM / 64, 1), 256>>>(GRD * DIM);
    conv_kernel<<<dim3(DIM / 64, GRD), 256>>>(DIM);
    convs1_kernel<<<GRD, GRD>>>();
    convs2_kernel<<<GRD, GRD>>>();
    final_kernel<<<(COMPS * DIM / 4 + 255) / 256, 256>>>(W, out, itp);
}

// round 11
// speedup vs baseline: 2.0010x; 1.4588x over previous
#include <cuda_runtime.h>
#include <cuda_bf16.h>
#include <math.h>
#include <cstdint>

#define BSZ   4096
#define DIM   768
#define COMPS 16384
#define GRD   128

// ---------------- device scratch ----------------
__device__ float g_T[COMPS * DIM];
__device__ float g_wn[COMPS];
__device__ float g_cnt[COMPS];
__device__ float g_s1[COMPS];
__device__ float g_s[COMPS];
__device__ float g_G[GRD * GRD];
__device__ int   g_bmu[BSZ];
__device__ __align__(16) __nv_bfloat16 g_Xb[BSZ * DIM];
__device__ __align__(16) __nv_bfloat16 g_Wb[COMPS * DIM];
__device__ __align__(16) float4 g_top2[(size_t)BSZ * 128];   // per (row, coltile): v0,i0,v1,i1

// ---------------- helpers ----------------
__device__ __forceinline__ uint32_t smem_to_u32(const void* p) {
    uint32_t a;
    asm("{ .reg .u64 t; cvta.to.shared.u64 t, %1; cvt.u32.u64 %0, t; }" : "=r"(a) : "l"(p));
    return a;
}
__device__ __forceinline__ void cp_async16(uint32_t dst, const void* src) {
    asm volatile("cp.async.cg.shared.global [%0], [%1], 16;" :: "r"(dst), "l"(src));
}
__device__ __forceinline__ uint32_t lds32(uint32_t a) {
    uint32_t v;
    asm volatile("ld.shared.b32 %0, [%1];" : "=r"(v) : "r"(a));
    return v;
}
__device__ __forceinline__ void mma_bf16(float* d, const uint32_t* a, const uint32_t* b) {
    asm volatile(
        "mma.sync.aligned.m16n8k16.row.col.f32.bf16.bf16.f32 "
        "{%0,%1,%2,%3}, {%4,%5,%6,%7}, {%8,%9}, {%0,%1,%2,%3};"
        : "+f"(d[0]), "+f"(d[1]), "+f"(d[2]), "+f"(d[3])
        : "r"(a[0]), "r"(a[1]), "r"(a[2]), "r"(a[3]), "r"(b[0]), "r"(b[1]));
}
__device__ __forceinline__ unsigned long long pack2(float lo, float hi) {
    unsigned long long r;
    asm("mov.b64 %0, {%1, %2};" : "=l"(r) : "r"(__float_as_uint(lo)), "r"(__float_as_uint(hi)));
    return r;
}
__device__ __forceinline__ void ffma2(unsigned long long& d, unsigned long long a,
                                      unsigned long long b) {
    asm("fma.rn.f32x2 %0, %1, %2, %0;" : "+l"(d) : "l"(a), "l"(b));
}
__device__ __forceinline__ void unpack2(unsigned long long p, float& lo, float& hi) {
    unsigned l, h;
    asm("mov.b64 {%0, %1}, %2;" : "=r"(l), "=r"(h) : "l"(p));
    lo = __uint_as_float(l); hi = __uint_as_float(h);
}

// ---------------- pre kernels ----------------
#define XN4 (BSZ * DIM / 4)
#define WN4 (COMPS * DIM / 4)

// fp32 -> bf16 convert (X)
__global__ void cvtX_kernel(const float* __restrict__ src) {
    int i = blockIdx.x * blockDim.x + threadIdx.x;
    if (i >= XN4) return;
    float4 v = *(const float4*)(src + (size_t)i * 4);
    ushort4 o;
    o.x = __bfloat16_as_ushort(__float2bfloat16(v.x));
    o.y = __bfloat16_as_ushort(__float2bfloat16(v.y));
    o.z = __bfloat16_as_ushort(__float2bfloat16(v.z));
    o.w = __bfloat16_as_ushort(__float2bfloat16(v.w));
    *(ushort4*)(g_Xb + (size_t)i * 4) = o;
}

// fp32 -> bf16 convert (W) + exact ||w||^2, one warp per row
__global__ void cvtW_wnorm_kernel(const float* __restrict__ W) {
    int row = blockIdx.x * 8 + (threadIdx.x >> 5);
    int lane = threadIdx.x & 31;
    const float* wr = W + (size_t)row * DIM;
    float s = 0.f;
    #pragma unroll
    for (int k = 0; k < 6; k++) {
        int e = lane * 4 + k * 128;
        float4 v = *(const float4*)(wr + e);
        s = fmaf(v.x, v.x, s); s = fmaf(v.y, v.y, s);
        s = fmaf(v.z, v.z, s); s = fmaf(v.w, v.w, s);
        ushort4 o;
        o.x = __bfloat16_as_ushort(__float2bfloat16(v.x));
        o.y = __bfloat16_as_ushort(__float2bfloat16(v.y));
        o.z = __bfloat16_as_ushort(__float2bfloat16(v.z));
        o.w = __bfloat16_as_ushort(__float2bfloat16(v.w));
        *(ushort4*)(g_Wb + (size_t)row * DIM + e) = o;
    }
    #pragma unroll
    for (int o = 16; o; o >>= 1) s += __shfl_xor_sync(0xffffffffu, s, o);
    if (lane == 0) g_wn[row] = s;
}

__global__ void gmat_kernel(const int* __restrict__ itp) {
    float decay = 1.f - (float)(*itp) / 1000.f;
    float sig = 64.f * decay;
    int a = blockIdx.x, b = threadIdx.x;
    float d = (float)(a - b);
    g_G[a * GRD + b] = expf(-(d * d) / (sig * sig));
}

// ---------------- bf16 BMU GEMM: 128x128 tiles, 2 CTAs/SM, 4 stages ------
// K chunk = 16 halfs = 32B/row, padded pitch 48B. Stage = A 6144 + B 6144.
#define QPITCH  48
#define QT_TILE 6144
#define QSTAGE  12288
#define QWNS    (4 * QSTAGE)     // 49152
#define QSMEM   (QWNS + 512)     // 49664
#define NKCH    (DIM / 16)       // 48

#define INS2(v, i)                                            \
    do {                                                      \
        float _v = (v); int _i = (i);                         \
        if (_v < v0) { v1 = v0; i1 = i0; v0 = _v; i0 = _i; }  \
        else if (_v < v1) { v1 = _v; i1 = _i; }               \
    } while (0)

__global__ __launch_bounds__(256, 2) void bmu_b_kernel() {
    extern __shared__ char sm[];
    const uint32_t sb = smem_to_u32(sm);
    const int t = threadIdx.x, lane = t & 31, w = t >> 5;
    const int wm = w >> 2, wn_ = w & 3;
    const int arow = lane >> 2, ac4 = (lane & 3) * 4;
    const int bx = blockIdx.x, by = blockIdx.y;
    const int rowX = by * 128, rowW = bx * 128;

    float* wns = (float*)(sm + QWNS);
    if (t < 128) wns[t] = g_wn[rowW + t];

    float acc[4][4][4];
    #pragma unroll
    for (int mi = 0; mi < 4; mi++)
        #pragma unroll
        for (int ni = 0; ni < 4; ni++)
            #pragma unroll
            for (int k = 0; k < 4; k++) acc[mi][ni][k] = 0.f;

    auto load_stage = [&](int s, int c) {
        uint32_t base = sb + s * QSTAGE;
        int r = t >> 1, g = t & 1;
        cp_async16(base + r * QPITCH + g * 16,
                   g_Xb + (size_t)(rowX + r) * DIM + c * 16 + g * 8);
        cp_async16(base + QT_TILE + r * QPITCH + g * 16,
                   g_Wb + (size_t)(rowW + r) * DIM + c * 16 + g * 8);
    };
    auto compute = [&](int s) {
        uint32_t Ah = sb + s * QSTAGE;
        uint32_t Bh = Ah + QT_TILE;
        uint32_t b[4][2];
        #pragma unroll
        for (int ni = 0; ni < 4; ni++) {
            uint32_t off = Bh + (uint32_t)((wn_ * 32 + ni * 8 + arow) * QPITCH + ac4);
            b[ni][0] = lds32(off); b[ni][1] = lds32(off + 16);
        }
        uint32_t a[4][4];
        #pragma unroll
        for (int mi = 0; mi < 4; mi++) {
            uint32_t off = Ah + (uint32_t)((wm * 64 + mi * 16 + arow) * QPITCH + ac4);
            a[mi][0] = lds32(off);      a[mi][1] = lds32(off + 8 * QPITCH);
            a[mi][2] = lds32(off + 16); a[mi][3] = lds32(off + 8 * QPITCH + 16);
        }
        #pragma unroll
        for (int mi = 0; mi < 4; mi++)
            #pragma unroll
            for (int ni = 0; ni < 4; ni++) mma_bf16(acc[mi][ni], a[mi], b[ni]);
    };

    #pragma unroll
    for (int p = 0; p < 3; p++) { load_stage(p, p); asm volatile("cp.async.commit_group;"); }
    for (int c = 0; c < NKCH; c++) {
        asm volatile("cp.async.wait_group 2;");
        __syncthreads();
        if (c + 3 < NKCH) load_stage((c + 3) & 3, c + 3);
        asm volatile("cp.async.commit_group;");
        compute(c & 3);
    }

    // ---- epilogue: per-row top-2 of d2 = wn - 2*dot over 128 cols ----
    __syncthreads();                       // stage smem free for reuse
    float4* top2s = (float4*)sm;           // [128 rows][4 warps]

    #pragma unroll
    for (int mi = 0; mi < 4; mi++) {
        #pragma unroll
        for (int h = 0; h < 2; h++) {
            float v0 = 3.4e38f, v1 = 3.4e38f;
            int i0 = 0x7fffffff, i1 = 0x7fffffff;
            #pragma unroll
            for (int ni = 0; ni < 4; ni++) {
                #pragma unroll
                for (int cc = 0; cc < 2; cc++) {
                    int col = wn_ * 32 + ni * 8 + (lane & 3) * 2 + cc;
                    float d2 = wns[col] - 2.f * acc[mi][ni][h * 2 + cc];
                    INS2(d2, rowW + col);
                }
            }
            #pragma unroll
            for (int o = 1; o < 4; o <<= 1) {
                float ov0 = __shfl_xor_sync(0xffffffffu, v0, o);
                int   oi0 = __shfl_xor_sync(0xffffffffu, i0, o);
                float ov1 = __shfl_xor_sync(0xffffffffu, v1, o);
                int   oi1 = __shfl_xor_sync(0xffffffffu, i1, o);
                INS2(ov0, oi0);
                INS2(ov1, oi1);
            }
            if ((lane & 3) == 0) {
                int rr = wm * 64 + mi * 16 + h * 8 + arow;
                top2s[rr * 4 + wn_] = make_float4(v0, __int_as_float(i0),
                                                  v1, __int_as_float(i1));
            }
        }
    }
    __syncthreads();
    if (t < 128) {
        float4 a0 = top2s[t * 4 + 0];
        float v0 = a0.x, v1 = a0.z;
        int i0 = __float_as_int(a0.y), i1 = __float_as_int(a0.w);
        #pragma unroll
        for (int j = 1; j < 4; j++) {
            float4 aj = top2s[t * 4 + j];
            INS2(aj.x, __float_as_int(aj.y));
            INS2(aj.z, __float_as_int(aj.w));
        }
        g_top2[(size_t)(rowX + t) * 128 + bx] =
            make_float4(v0, __int_as_float(i0), v1, __int_as_float(i1));
    }
}

// ---------------- candidate rescue: min + margin over top-2 + exact fp32 --
#define MARGIN_F 2.0f
__global__ __launch_bounds__(128) void bmu_scan_kernel(const float* __restrict__ X,
                                                       const float* __restrict__ W) {
    __shared__ float red[128];
    __shared__ int cnt;
    __shared__ int cand[128];
    int row = blockIdx.x, t = threadIdx.x;
    float4 e = g_top2[(size_t)row * 128 + t];

    red[t] = e.x;
    __syncthreads();
    for (int s = 64; s; s >>= 1) {
        if (t < s) red[t] = fminf(red[t], red[t + s]);
        __syncthreads();
    }
    float thr = red[0] + MARGIN_F;
    if (t == 0) cnt = 0;
    __syncthreads();
    if (e.x <= thr) { int p = atomicAdd(&cnt, 1); if (p < 128) cand[p] = __float_as_int(e.y); }
    if (e.z <= thr) { int p = atomicAdd(&cnt, 1); if (p < 128) cand[p] = __float_as_int(e.w); }
    __syncthreads();
    int n = min(cnt, 128);
    if (t < 32) {
        const float* xr = X + (size_t)row * DIM;
        float bv = 3.4e38f; int bi = 0x7fffffff;
        for (int k = 0; k < n; k++) {
            int c = cand[k];
            const float* wr = W + (size_t)c * DIM;
            float s = 0.f;
            #pragma unroll
            for (int m = 0; m < 24; m++)
                s = fmaf(xr[t + m * 32], wr[t + m * 32], s);
            #pragma unroll
            for (int o = 16; o; o >>= 1) s += __shfl_xor_sync(0xffffffffu, s, o);
            float d2 = g_wn[c] - 2.f * s;
            if (d2 < bv || (d2 == bv && c < bi)) { bv = d2; bi = c; }
        }
        if (t == 0) g_bmu[row] = bi;
    }
}

__global__ void scatter_kernel(const float* __restrict__ X) {
    int b = blockIdx.x;
    int u = g_bmu[b];
    const float* xr = X + (size_t)b * DIM;
    float* tr = g_T + (size_t)u * DIM;
    for (int d = threadIdx.x; d < DIM; d += blockDim.x)
        atomicAdd(&tr[d], xr[d]);
    if (threadIdx.x == 0) atomicAdd(&g_cnt[u], 1.f);
}

// ---------------- separable Gaussian conv via packed f32x2, in place ------
__global__ __launch_bounds__(256) void conv_kernel(int rstride) {
    __shared__ float Ts[16][64];
    __shared__ float Gs[16][128];
    int t = threadIdx.x;
    size_t base = (size_t)blockIdx.y * (GRD * DIM) + (size_t)blockIdx.x * 64;
    int cg = t & 15, rg = t >> 4;
    int lk = t >> 4, lc = (t & 15) * 4, gi = (t & 15) * 8;

    unsigned long long acc2[8][2];
    #pragma unroll
    for (int r = 0; r < 8; r++) { acc2[r][0] = 0ull; acc2[r][1] = 0ull; }

    for (int k0 = 0; k0 < GRD; k0 += 16) {
        if (k0) __syncthreads();
        *(float4*)&Ts[lk][lc]     = *(const float4*)&g_T[base + (size_t)(k0 + lk) * rstride + lc];
        *(float4*)&Gs[lk][gi]     = *(const float4*)&g_G[(k0 + lk) * GRD + gi];
        *(float4*)&Gs[lk][gi + 4] = *(const float4*)&g_G[(k0 + lk) * GRD + gi + 4];
        __syncthreads();
        #pragma unroll
        for (int k = 0; k < 16; k++) {
            float4 tv = *(const float4*)&Ts[k][cg * 4];
            unsigned long long b0 = pack2(tv.x, tv.y);
            unsigned long long b1 = pack2(tv.z, tv.w);
            #pragma unroll
            for (int r = 0; r < 8; r++) {
                float g = Gs[k][rg * 8 + r];
                unsigned long long gp = pack2(g, g);
                ffma2(acc2[r][0], gp, b0);
                ffma2(acc2[r][1], gp, b1);
            }
        }
    }
    #pragma unroll
    for (int r = 0; r < 8; r++) {
        float4 o;
        unpack2(acc2[r][0], o.x, o.y);
        unpack2(acc2[r][1], o.z, o.w);
        *(float4*)&g_T[base + (size_t)(rg * 8 + r) * rstride + cg * 4] = o;
    }
}

__global__ void convs1_kernel() {
    int ip = blockIdx.x, j = threadIdx.x;
    float s = 0.f;
    for (int i = 0; i < GRD; i++)
        s = fmaf(g_G[ip * GRD + i], g_cnt[i * GRD + j], s);
    g_s1[ip * GRD + j] = s;
}
__global__ void convs2_kernel() {
    int i = blockIdx.x, jp = threadIdx.x;
    float s = 0.f;
    for (int j = 0; j < GRD; j++)
        s = fmaf(g_G[j * GRD + jp], g_s1[i * GRD + j], s);
    g_s[i * GRD + jp] = s;
}

__global__ void final_kernel(const float* __restrict__ W, float* __restrict__ out,
                             const int* __restrict__ itp) {
    float decay = 1.f - (float)(*itp) / 1000.f;
    float alpha = 0.3f * decay;
    int idx = blockIdx.x * blockDim.x + threadIdx.x;
    int i4 = idx * 4;
    if (i4 >= COMPS * DIM) return;
    int c = i4 / DIM;
    float m = 1.f - alpha * g_s[c];
    float4 w = *(const float4*)(W + i4);
    float4 v = *(const float4*)(g_T + i4);
    float4 o = make_float4(w.x * m + alpha * v.x, w.y * m + alpha * v.y,
                           w.z * m + alpha * v.z, w.w * m + alpha * v.w);
    *(float4*)(out + i4) = o;
}

// ---------------- launch ----------------
extern "C" void kernel_launch(void* const* d_in, const int* in_sizes, int n_in,
                              void* d_out, int out_size) {
    const float* X   = (const float*)d_in[0];
    const float* W   = (const float*)d_in[1];
    const int*   itp = (const int*)d_in[2];
    float* out = (float*)d_out;

    cudaFuncSetAttribute(bmu_b_kernel, cudaFuncAttributeMaxDynamicSharedMemorySize, QSMEM);

    float *tPtr, *cntPtr;
    cudaGetSymbolAddress((void**)&tPtr, g_T);
    cudaGetSymbolAddress((void**)&cntPtr, g_cnt);

    cvtX_kernel<<<(XN4 + 255) / 256, 256>>>(X);                   // 0
    cvtW_wnorm_kernel<<<COMPS / 8, 256>>>(W);                     // 1
    gmat_kernel<<<GRD, GRD>>>(itp);                               // 2
    bmu_b_kernel<<<dim3(COMPS / 128, BSZ / 128), 256, QSMEM>>>(); // 3  (ncu slot 3)
    cudaMemsetAsync(tPtr, 0, (size_t)COMPS * DIM * sizeof(float));
    cudaMemsetAsync(cntPtr, 0, COMPS * sizeof(float));
    bmu_scan_kernel<<<BSZ, 128>>>(X, W);
    scatter_kernel<<<BSZ, 256>>>(X);
    conv_kernel<<<dim3(GRD * DIM / 64, 1), 256>>>(GRD * DIM);
    conv_kernel<<<dim3(DIM / 64, GRD), 256>>>(DIM);
    convs1_kernel<<<GRD, GRD>>>();
    convs2_kernel<<<GRD, GRD>>>();
    final_kernel<<<(COMPS * DIM / 4 + 255) / 256, 256>>>(W, out, itp);
}